// round 6
// baseline (speedup 1.0000x reference)
#include <cuda_runtime.h>
#include <math.h>

// Problem constants
#define BT  16384   // B*T
#define TT  2048    // T
#define CC  1024    // C
#define HH  16      // heads
#define DD  64      // head dim
#define DLOW 64

// ---------------------------------------------------------------------------
// Scratch: one __device__ global (no allocations allowed anywhere).
// Aliased lifetimes to keep it small (~322 MB):
//   buf0: r                (live: gemm_r .. epi)
//   buf1: k  -> kk         (kv_kernel overwrites in-place; read-before-write)
//   buf2: v                (live: gemm_v .. epi)
//   buf3: gate -> xng      (epi overwrites in-place; read-before-write)
//   buf4: kv -> wkv        (scan overwrites in-place; read-before-write)
//   small: hw, ha, hg  (BT*64 each), wdec, abuf (BT*16 each)
// ---------------------------------------------------------------------------
#define S_BIG   ((size_t)BT * CC)            // 16777216 floats = 64 MB
#define OFF_R    ((size_t)0)
#define OFF_K    ((size_t)1 * S_BIG)         // aliases KK
#define OFF_V    ((size_t)2 * S_BIG)
#define OFF_GATE ((size_t)3 * S_BIG)         // aliases XNG
#define OFF_KV   ((size_t)4 * S_BIG)         // aliases WKV
#define OFF_HW   ((size_t)5 * S_BIG)
#define OFF_HA   (OFF_HW + (size_t)BT * 64)
#define OFF_HG   (OFF_HA + (size_t)BT * 64)
#define OFF_WD   (OFF_HG + (size_t)BT * 64)
#define OFF_AB   (OFF_WD + (size_t)BT * HH)
#define SCR_TOTAL (OFF_AB + (size_t)BT * HH)

__device__ float g_scr[SCR_TOTAL];

// ---------------------------------------------------------------------------
// Epilogue ops
// ---------------------------------------------------------------------------
#define EPI_NONE 0
#define EPI_TANH 1
#define EPI_SIG  2

template <int EPI>
__device__ __forceinline__ float epi_apply(float x) {
    if (EPI == EPI_TANH) return tanhf(x);
    if (EPI == EPI_SIG)  return 1.0f / (1.0f + expf(-x));
    return x;
}

// A-fragment loader: optionally fuses the token-shift mix
//   a = x + (x - x_prev) * coef  (prev = 0 at t == 0; T = 2048 is pow2)
template <bool MIX>
__device__ __forceinline__ float4 load_a_frag(const float* __restrict__ A,
                                              const float* __restrict__ coef,
                                              int m, int K, int kidx) {
    float4 cur = *(const float4*)(A + (size_t)m * K + kidx);
    if (MIX) {
        float4 pr = make_float4(0.f, 0.f, 0.f, 0.f);
        if ((m & (TT - 1)) != 0)
            pr = *(const float4*)(A + (size_t)(m - 1) * K + kidx);
        float4 cf = *(const float4*)(coef + kidx);
        cur.x = fmaf(cur.x - pr.x, cf.x, cur.x);
        cur.y = fmaf(cur.y - pr.y, cf.y, cur.y);
        cur.z = fmaf(cur.z - pr.z, cf.z, cur.z);
        cur.w = fmaf(cur.w - pr.w, cf.w, cur.w);
    }
    return cur;
}

// ---------------------------------------------------------------------------
// SGEMM: C[M,N] = epi(A'[M,K] @ B[K,N]), A' = mixed(A) when MIX.
// BM=128, BK=16, TM=8. BN/TN templated (128/8 for wide, 64/4 for lora).
// Double-buffered smem, register-staged global prefetch: 1 barrier per K-tile.
// M % 128 == 0, N % BN == 0, K % 16 == 0 assumed (true for all our shapes).
// ---------------------------------------------------------------------------
template <int BN, int TN, int EPI, bool MIX>
__global__ void __launch_bounds__(256)
gemm_kernel(const float* __restrict__ A, const float* __restrict__ coef,
            const float* __restrict__ B, float* __restrict__ C,
            int M, int N, int K) {
    constexpr int BM = 128, BK = 16, TM = 8;
    constexpr int NTH = 256;
    constexpr int BKV = (BK * BN / 4) / NTH;      // float4 B loads per thread
    constexpr int BCOLS4 = BN / 4;
    constexpr int BROWSTEP = NTH / BCOLS4;

    __shared__ float As[2][BK][BM + 4];
    __shared__ float Bs[2][BK][BN];

    const int tid = threadIdx.x;
    const int bm = blockIdx.y;
    const int bn = blockIdx.x;

    const int tn = tid % (BN / TN);
    const int tm = tid / (BN / TN);

    const int arow = tid >> 2;                    // 0..63
    const int acol = (tid & 3) * 4;               // 0,4,8,12
    const int brow0 = tid / BCOLS4;
    const int bcol  = (tid % BCOLS4) * 4;

    float acc[TM][TN];
#pragma unroll
    for (int i = 0; i < TM; i++)
#pragma unroll
        for (int j = 0; j < TN; j++) acc[i][j] = 0.f;

    const int nk = K / BK;

    float4 aReg[2];
    float4 bReg[BKV];

    // prologue: tile 0 -> regs -> smem[0]
#pragma unroll
    for (int p = 0; p < 2; p++)
        aReg[p] = load_a_frag<MIX>(A, coef, bm * BM + arow + p * 64, K, acol);
#pragma unroll
    for (int q = 0; q < BKV; q++)
        bReg[q] = *(const float4*)(B + (size_t)(brow0 + q * BROWSTEP) * N + bn * BN + bcol);

#pragma unroll
    for (int p = 0; p < 2; p++) {
        As[0][acol + 0][arow + p * 64] = aReg[p].x;
        As[0][acol + 1][arow + p * 64] = aReg[p].y;
        As[0][acol + 2][arow + p * 64] = aReg[p].z;
        As[0][acol + 3][arow + p * 64] = aReg[p].w;
    }
#pragma unroll
    for (int q = 0; q < BKV; q++)
        *(float4*)&Bs[0][brow0 + q * BROWSTEP][bcol] = bReg[q];
    __syncthreads();

    int cur = 0;
    for (int kt = 0; kt < nk; kt++) {
        if (kt + 1 < nk) {
            const int kb = (kt + 1) * BK;
#pragma unroll
            for (int p = 0; p < 2; p++)
                aReg[p] = load_a_frag<MIX>(A, coef, bm * BM + arow + p * 64, K, kb + acol);
#pragma unroll
            for (int q = 0; q < BKV; q++)
                bReg[q] = *(const float4*)(B + (size_t)(kb + brow0 + q * BROWSTEP) * N + bn * BN + bcol);
        }

#pragma unroll
        for (int kk = 0; kk < BK; kk++) {
            float av[TM], bv[TN];
#pragma unroll
            for (int i = 0; i < TM; i += 4)
                *(float4*)&av[i] = *(const float4*)&As[cur][kk][tm * TM + i];
#pragma unroll
            for (int j = 0; j < TN; j += 4)
                *(float4*)&bv[j] = *(const float4*)&Bs[cur][kk][tn * TN + j];
#pragma unroll
            for (int i = 0; i < TM; i++)
#pragma unroll
                for (int j = 0; j < TN; j++)
                    acc[i][j] = fmaf(av[i], bv[j], acc[i][j]);
        }

        if (kt + 1 < nk) {
            const int nxt = cur ^ 1;
#pragma unroll
            for (int p = 0; p < 2; p++) {
                As[nxt][acol + 0][arow + p * 64] = aReg[p].x;
                As[nxt][acol + 1][arow + p * 64] = aReg[p].y;
                As[nxt][acol + 2][arow + p * 64] = aReg[p].z;
                As[nxt][acol + 3][arow + p * 64] = aReg[p].w;
            }
#pragma unroll
            for (int q = 0; q < BKV; q++)
                *(float4*)&Bs[nxt][brow0 + q * BROWSTEP][bcol] = bReg[q];
            __syncthreads();
            cur = nxt;
        }
    }

    // epilogue
#pragma unroll
    for (int i = 0; i < TM; i++) {
        const int row = bm * BM + tm * TM + i;
        float* crow = C + (size_t)row * N + bn * BN + tn * TN;
#pragma unroll
        for (int j = 0; j < TN; j += 4) {
            float4 o;
            o.x = epi_apply<EPI>(acc[i][j + 0]);
            o.y = epi_apply<EPI>(acc[i][j + 1]);
            o.z = epi_apply<EPI>(acc[i][j + 2]);
            o.w = epi_apply<EPI>(acc[i][j + 3]);
            *(float4*)(crow + j) = o;
        }
    }
}

// ---------------------------------------------------------------------------
// decay w and in-context lr a:  one thread per (token, head)
//   z_w = w0[h] + hw[token,:] @ w2[:,h]   ->  w = e^{-0.5} * sigmoid(z_w)
//   z_a = a0[h] + ha[token,:] @ a2[:,h]   ->  a = sigmoid(z_a)
// hw/ha already have tanh applied (GEMM epilogue).
// ---------------------------------------------------------------------------
__global__ void wa_kernel(const float* __restrict__ hw, const float* __restrict__ ha,
                          const float* __restrict__ w2, const float* __restrict__ a2,
                          const float* __restrict__ w0, const float* __restrict__ a0,
                          float* __restrict__ wout, float* __restrict__ aout) {
    const int idx = blockIdx.x * blockDim.x + threadIdx.x;   // BT*HH threads
    const int token = idx >> 4;
    const int h = idx & 15;
    const float* hwr = hw + (size_t)token * 64;
    const float* har = ha + (size_t)token * 64;
    float sw = 0.f, sa = 0.f;
#pragma unroll
    for (int kx = 0; kx < 64; kx++) {
        sw = fmaf(hwr[kx], w2[kx * HH + h], sw);
        sa = fmaf(har[kx], a2[kx * HH + h], sa);
    }
    const float zw = w0[h] + sw;
    wout[idx] = 0.60653065971263342f / (1.f + expf(-zw));     // e^{-0.5} * sigmoid(zw)
    aout[idx] = 1.f / (1.f + expf(-(a0[h] + sa)));
}

// ---------------------------------------------------------------------------
// kk = normalize((k*k_k) per head), kv = kk * v * a.  One warp per (token,h).
// kkout may alias k (read-before-write at identical indices).
// ---------------------------------------------------------------------------
__global__ void kv_kernel(const float* __restrict__ k, const float* __restrict__ v,
                          const float* __restrict__ k_k, const float* __restrict__ abuf,
                          float* __restrict__ kkout, float* __restrict__ kvout) {
    const int gw = (blockIdx.x * blockDim.x + threadIdx.x) >> 5;
    const int lane = threadIdx.x & 31;
    const int token = gw >> 4;
    const int h = gw & 15;
    const size_t base = (size_t)token * CC + h * DD;
    const int c0 = h * DD + lane, c1 = c0 + 32;

    float k0 = k[base + lane]       * k_k[c0];
    float k1 = k[base + lane + 32]  * k_k[c1];
    float ss = k0 * k0 + k1 * k1;
#pragma unroll
    for (int o = 16; o; o >>= 1) ss += __shfl_xor_sync(0xffffffffu, ss, o);
    const float inv = 1.f / fmaxf(sqrtf(ss), 1e-12f);
    k0 *= inv; k1 *= inv;
    const float a = abuf[(size_t)token * HH + h];
    const float vv0 = v[base + lane], vv1 = v[base + lane + 32];
    kkout[base + lane]      = k0;
    kkout[base + lane + 32] = k1;
    kvout[base + lane]      = k0 * vv0 * a;
    kvout[base + lane + 32] = k1 * vv1 * a;
}

// ---------------------------------------------------------------------------
// WKV scan: state = state * w_t + kv_t, inclusive states stored.
// One block per (b,h), 64 threads (one per d). Serial over T.
// wkv may alias kv (each element read once, then overwritten).
// ---------------------------------------------------------------------------
__global__ void scan_kernel(const float* __restrict__ kv, const float* __restrict__ wdec,
                            float* __restrict__ wkv) {
    const int bh = blockIdx.x;            // 0..127
    const int b = bh >> 4, h = bh & 15;
    const int d = threadIdx.x;            // 0..63
    const size_t base = (size_t)b * TT * CC + (size_t)h * DD + d;
    const float* kvp = kv + base;
    float* op = wkv + base;
    const float* wp = wdec + (size_t)b * TT * HH + h;
    float state = 0.f;
#pragma unroll 8
    for (int t = 0; t < TT; t++) {
        const float w = wp[(size_t)t * HH];
        const float x = kvp[(size_t)t * CC];
        state = fmaf(state, w, x);
        op[(size_t)t * CC] = state;
    }
}

// ---------------------------------------------------------------------------
// Fused epilogue: bonus + GroupNorm + affine + gate. One warp per (token,h).
//   x = state*r + (sum_d r*kk*r_k) * v
//   xn = (x - mean) * rsqrt(var + 1e-5) * ln_w + ln_b ;  out = xn * g
// xng may alias g (read-before-write at identical indices).
// ---------------------------------------------------------------------------
__global__ void epi_kernel(const float* __restrict__ wkv, const float* __restrict__ r,
                           const float* __restrict__ kk, const float* __restrict__ v,
                           const float* __restrict__ r_k, const float* __restrict__ g,
                           const float* __restrict__ lnw, const float* __restrict__ lnb,
                           float* __restrict__ xng) {
    const int gw = (blockIdx.x * blockDim.x + threadIdx.x) >> 5;
    const int lane = threadIdx.x & 31;
    const int token = gw >> 4;
    const int h = gw & 15;
    const size_t base = (size_t)token * CC + h * DD;
    const int c0 = h * DD + lane, c1 = c0 + 32;

    const float s0 = wkv[base + lane],      s1 = wkv[base + lane + 32];
    const float r0 = r[base + lane],        r1 = r[base + lane + 32];
    const float q0 = kk[base + lane],       q1 = kk[base + lane + 32];
    const float v0 = v[base + lane],        v1 = v[base + lane + 32];
    const float g0 = g[base + lane],        g1v = g[base + lane + 32];

    float bsum = r0 * q0 * r_k[c0] + r1 * q1 * r_k[c1];
#pragma unroll
    for (int o = 16; o; o >>= 1) bsum += __shfl_xor_sync(0xffffffffu, bsum, o);

    const float x0 = fmaf(bsum, v0, s0 * r0);
    const float x1 = fmaf(bsum, v1, s1 * r1);

    float ms = x0 + x1;
    float vs = x0 * x0 + x1 * x1;
#pragma unroll
    for (int o = 16; o; o >>= 1) {
        ms += __shfl_xor_sync(0xffffffffu, ms, o);
        vs += __shfl_xor_sync(0xffffffffu, vs, o);
    }
    const float mean = ms * (1.f / 64.f);
    const float var  = vs * (1.f / 64.f) - mean * mean;
    const float rs = rsqrtf(var + 1e-5f);

    xng[base + lane]      = fmaf((x0 - mean) * rs, lnw[c0], lnb[c0]) * g0;
    xng[base + lane + 32] = fmaf((x1 - mean) * rs, lnw[c1], lnb[c1]) * g1v;
}

// ---------------------------------------------------------------------------
// Host launch
// ---------------------------------------------------------------------------
extern "C" void kernel_launch(void* const* d_in, const int* in_sizes, int n_in,
                              void* d_out, int out_size) {
    (void)in_sizes; (void)n_in; (void)out_size;
    const float* x   = (const float*)d_in[0];
    const float* x_r = (const float*)d_in[1];
    const float* x_w = (const float*)d_in[2];
    const float* x_k = (const float*)d_in[3];
    const float* x_v = (const float*)d_in[4];
    const float* x_a = (const float*)d_in[5];
    const float* x_g = (const float*)d_in[6];
    const float* w0  = (const float*)d_in[7];
    const float* w1  = (const float*)d_in[8];
    const float* w2  = (const float*)d_in[9];
    const float* a0  = (const float*)d_in[10];
    const float* a1  = (const float*)d_in[11];
    const float* a2  = (const float*)d_in[12];
    // d_in[13..15] = v0, v1, v2 : mathematically a no-op in the reference
    const float* g1  = (const float*)d_in[16];
    const float* g2  = (const float*)d_in[17];
    const float* k_k = (const float*)d_in[18];
    const float* r_k = (const float*)d_in[19];
    const float* Wr  = (const float*)d_in[20];
    const float* Wk  = (const float*)d_in[21];
    const float* Wv  = (const float*)d_in[22];
    const float* Wo  = (const float*)d_in[23];
    const float* lnw = (const float*)d_in[24];
    const float* lnb = (const float*)d_in[25];
    float* out = (float*)d_out;

    float* scr = nullptr;
    cudaGetSymbolAddress((void**)&scr, g_scr);

    float* rB   = scr + OFF_R;
    float* kB   = scr + OFF_K;      // becomes kk in-place
    float* vB   = scr + OFF_V;
    float* gate = scr + OFF_GATE;   // becomes xng in-place
    float* kvB  = scr + OFF_KV;     // becomes wkv in-place
    float* hw   = scr + OFF_HW;
    float* ha   = scr + OFF_HA;
    float* hg   = scr + OFF_HG;
    float* wd   = scr + OFF_WD;
    float* ab   = scr + OFF_AB;

    const dim3 gridBig(CC / 128, BT / 128);       // (8, 128)
    const dim3 gridLora(1, BT / 128);             // (1, 128)

    // 1) big projections with fused token-shift mix
    gemm_kernel<128, 8, EPI_NONE, true><<<gridBig, 256>>>(x, x_r, Wr, rB, BT, CC, CC);
    gemm_kernel<128, 8, EPI_NONE, true><<<gridBig, 256>>>(x, x_k, Wk, kB, BT, CC, CC);
    gemm_kernel<128, 8, EPI_NONE, true><<<gridBig, 256>>>(x, x_v, Wv, vB, BT, CC, CC);

    // 2) lora stage 1 (tanh fused)
    gemm_kernel<64, 4, EPI_TANH, true><<<gridLora, 256>>>(x, x_w, w1, hw, BT, DLOW, CC);
    gemm_kernel<64, 4, EPI_TANH, true><<<gridLora, 256>>>(x, x_a, a1, ha, BT, DLOW, CC);
    gemm_kernel<64, 4, EPI_TANH, true><<<gridLora, 256>>>(x, x_g, g1, hg, BT, DLOW, CC);

    // 3) decay + in-context lr
    wa_kernel<<<(BT * HH) / 256, 256>>>(hw, ha, w2, a2, w0, a0, wd, ab);

    // 4) gate stage 2 (sigmoid fused)
    gemm_kernel<128, 8, EPI_SIG, false><<<gridBig, 256>>>(hg, nullptr, g2, gate, BT, CC, DLOW);

    // 5) kk normalize + kv  (kk overwrites k in-place)
    kv_kernel<<<(BT * HH) / 8, 256>>>(kB, vB, k_k, ab, kB, kvB);

    // 6) WKV recurrence (wkv overwrites kv in-place)
    scan_kernel<<<8 * HH, 64>>>(kvB, wd, kvB);

    // 7) bonus + GroupNorm + gate (xng overwrites gate in-place)
    epi_kernel<<<(BT * HH) / 8, 256>>>(kvB, rB, kB, vB, r_k, gate, lnw, lnb, gate);

    // 8) output projection
    gemm_kernel<128, 8, EPI_NONE, false><<<gridBig, 256>>>(gate, nullptr, Wo, out, BT, CC, CC);
}

// round 7
// speedup vs baseline: 1.8361x; 1.8361x over previous
#include <cuda_runtime.h>
#include <math.h>
#include <stdint.h>

// Problem constants
#define BT  16384   // B*T
#define TT  2048    // T
#define CC  1024    // C
#define HH  16      // heads
#define DD  64      // head dim
#define DLOW 64

// ---------------------------------------------------------------------------
// Scratch (aliased lifetimes, ~322 MB)
// ---------------------------------------------------------------------------
#define S_BIG   ((size_t)BT * CC)
#define OFF_R    ((size_t)0)
#define OFF_K    ((size_t)1 * S_BIG)         // aliases KK
#define OFF_V    ((size_t)2 * S_BIG)
#define OFF_GATE ((size_t)3 * S_BIG)         // aliases XNG
#define OFF_KV   ((size_t)4 * S_BIG)         // aliases WKV
#define OFF_HW   ((size_t)5 * S_BIG)
#define OFF_HA   (OFF_HW + (size_t)BT * 64)
#define OFF_HG   (OFF_HA + (size_t)BT * 64)
#define OFF_WD   (OFF_HG + (size_t)BT * 64)
#define OFF_AB   (OFF_WD + (size_t)BT * HH)
#define SCR_TOTAL (OFF_AB + (size_t)BT * HH)

__device__ float g_scr[SCR_TOTAL];

// ---------------------------------------------------------------------------
// Helpers
// ---------------------------------------------------------------------------
#define EPI_NONE 0
#define EPI_TANH 1
#define EPI_SIG  2

template <int EPI>
__device__ __forceinline__ float epi_apply(float x) {
    if (EPI == EPI_TANH) return tanhf(x);
    if (EPI == EPI_SIG)  return 1.0f / (1.0f + expf(-x));
    return x;
}

__device__ __forceinline__ float to_tf32(float x) {
    uint32_t o;
    asm("cvt.rna.tf32.f32 %0, %1;" : "=r"(o) : "f"(x));
    return __uint_as_float(o);
}

__device__ __forceinline__ void mma_tf32(float* c, const uint32_t* a,
                                         uint32_t b0, uint32_t b1) {
    asm("mma.sync.aligned.m16n8k8.row.col.f32.tf32.tf32.f32 "
        "{%0,%1,%2,%3}, {%4,%5,%6,%7}, {%8,%9}, {%0,%1,%2,%3};"
        : "+f"(c[0]), "+f"(c[1]), "+f"(c[2]), "+f"(c[3])
        : "r"(a[0]), "r"(a[1]), "r"(a[2]), "r"(a[3]), "r"(b0), "r"(b1));
}

// A-fragment loader: optionally fuses the token-shift mix
//   a = x + (x - x_prev) * coef  (prev = 0 at t == 0; T = 2048 is pow2)
template <bool MIX>
__device__ __forceinline__ float4 load_a_frag(const float* __restrict__ A,
                                              const float* __restrict__ coef,
                                              int m, int K, int kidx) {
    float4 cur = *(const float4*)(A + (size_t)m * K + kidx);
    if (MIX) {
        float4 pr = make_float4(0.f, 0.f, 0.f, 0.f);
        if ((m & (TT - 1)) != 0)
            pr = *(const float4*)(A + (size_t)(m - 1) * K + kidx);
        float4 cf = *(const float4*)(coef + kidx);
        cur.x = fmaf(cur.x - pr.x, cf.x, cur.x);
        cur.y = fmaf(cur.y - pr.y, cf.y, cur.y);
        cur.z = fmaf(cur.z - pr.z, cf.z, cur.z);
        cur.w = fmaf(cur.w - pr.w, cf.w, cur.w);
    }
    return cur;
}

// ---------------------------------------------------------------------------
// TF32 tensor-core GEMM: C[M,N] = epi(A'[M,K] @ B[K,N]), A' = mix(A) if MIX.
// BM=128, BK=32, 256 threads (8 warps). BN in {128, 64}.
// Double-buffered dynamic smem, register-staged prefetch, 1 barrier/K-tile.
// smem layouts (conflict-free fragment loads):
//   As[buf][m][k]  stride ASTR=36  (direct float4 STS from row-major A)
//   Bs[buf][k][n]  stride BSTR=BN+8 (direct float4 STS from row-major B)
// ---------------------------------------------------------------------------
template <int BN, int EPI, bool MIX>
__global__ void __launch_bounds__(256)
mma_gemm(const float* __restrict__ A, const float* __restrict__ coef,
         const float* __restrict__ B, float* __restrict__ C,
         int M, int N, int K) {
    constexpr int BM = 128, BK = 32;
    constexpr int WARPS_N = (BN == 128) ? 4 : 2;
    constexpr int WARPS_M = 8 / WARPS_N;
    constexpr int WM = BM / WARPS_M;          // 64 or 32
    constexpr int WN = BN / WARPS_N;          // 32
    constexpr int MT = WM / 16;               // 4 or 2
    constexpr int NT = WN / 8;                // 4
    constexpr int ASTR = BK + 4;              // 36 floats (16B-aligned rows)
    constexpr int BSTR = BN + 8;              // 136 or 72
    constexpr int BCOL4 = BN / 4;             // float4 columns of B tile
    constexpr int BKR = 256 / BCOL4;          // k-rows per load pass
    constexpr int BQ = BK / BKR;              // passes

    extern __shared__ float sm[];
    float* AsBase = sm;                       // [2][BM][ASTR]
    float* BsBase = sm + 2 * BM * ASTR;       // [2][BK][BSTR]

    const int tid = threadIdx.x;
    const int bm = blockIdx.y, bn = blockIdx.x;
    const int wid = tid >> 5, lane = tid & 31;
    const int lr = lane >> 2, lc = lane & 3;
    const int wM = wid / WARPS_N, wN = wid % WARPS_N;

    // A loader: thread -> (row am, 16-col half ak0), 4 float4 per tile
    const int am = tid >> 1;
    const int ak0 = (tid & 1) * 16;
    const int gm = bm * BM + am;
    // B loader
    const int bkr = tid / BCOL4;
    const int bnc = (tid % BCOL4) * 4;

    float acc[MT][NT][4];
#pragma unroll
    for (int i = 0; i < MT; i++)
#pragma unroll
        for (int j = 0; j < NT; j++)
#pragma unroll
            for (int q = 0; q < 4; q++) acc[i][j][q] = 0.f;

    const int nk = K / BK;
    float4 aR[4];
    float4 bR[BQ];

    // --- prologue: fetch tile 0 ---
#pragma unroll
    for (int q = 0; q < 4; q++)
        aR[q] = load_a_frag<MIX>(A, coef, gm, K, ak0 + q * 4);
#pragma unroll
    for (int q = 0; q < BQ; q++)
        bR[q] = *(const float4*)(B + (size_t)(bkr + q * BKR) * N + bn * BN + bnc);

    {
        float* Asb = AsBase;
        float* Bsb = BsBase;
#pragma unroll
        for (int q = 0; q < 4; q++) {
            float4 t4 = aR[q];
            t4.x = to_tf32(t4.x); t4.y = to_tf32(t4.y);
            t4.z = to_tf32(t4.z); t4.w = to_tf32(t4.w);
            *(float4*)(Asb + am * ASTR + ak0 + q * 4) = t4;
        }
#pragma unroll
        for (int q = 0; q < BQ; q++) {
            float4 t4 = bR[q];
            t4.x = to_tf32(t4.x); t4.y = to_tf32(t4.y);
            t4.z = to_tf32(t4.z); t4.w = to_tf32(t4.w);
            *(float4*)(Bsb + (bkr + q * BKR) * BSTR + bnc) = t4;
        }
    }
    __syncthreads();

    int cur = 0;
    for (int kt = 0; kt < nk; kt++) {
        if (kt + 1 < nk) {
            const int kb = (kt + 1) * BK;
#pragma unroll
            for (int q = 0; q < 4; q++)
                aR[q] = load_a_frag<MIX>(A, coef, gm, K, kb + ak0 + q * 4);
#pragma unroll
            for (int q = 0; q < BQ; q++)
                bR[q] = *(const float4*)(B + (size_t)(kb + bkr + q * BKR) * N + bn * BN + bnc);
        }

        const float* Asb = AsBase + cur * BM * ASTR;
        const float* Bsb = BsBase + cur * BK * BSTR;
#pragma unroll
        for (int ks = 0; ks < BK / 8; ks++) {
            const int k0 = ks * 8;
            uint32_t af[MT][4];
#pragma unroll
            for (int mt = 0; mt < MT; mt++) {
                const float* ap = Asb + (wM * WM + mt * 16 + lr) * ASTR + k0 + lc;
                af[mt][0] = __float_as_uint(ap[0]);
                af[mt][1] = __float_as_uint(ap[8 * ASTR]);
                af[mt][2] = __float_as_uint(ap[4]);
                af[mt][3] = __float_as_uint(ap[8 * ASTR + 4]);
            }
#pragma unroll
            for (int nt = 0; nt < NT; nt++) {
                const float* bp = Bsb + (k0 + lc) * BSTR + wN * WN + nt * 8 + lr;
                const uint32_t b0 = __float_as_uint(bp[0]);
                const uint32_t b1 = __float_as_uint(bp[4 * BSTR]);
#pragma unroll
                for (int mt = 0; mt < MT; mt++)
                    mma_tf32(acc[mt][nt], af[mt], b0, b1);
            }
        }

        if (kt + 1 < nk) {
            const int nxt = cur ^ 1;
            float* Asb2 = AsBase + nxt * BM * ASTR;
            float* Bsb2 = BsBase + nxt * BK * BSTR;
#pragma unroll
            for (int q = 0; q < 4; q++) {
                float4 t4 = aR[q];
                t4.x = to_tf32(t4.x); t4.y = to_tf32(t4.y);
                t4.z = to_tf32(t4.z); t4.w = to_tf32(t4.w);
                *(float4*)(Asb2 + am * ASTR + ak0 + q * 4) = t4;
            }
#pragma unroll
            for (int q = 0; q < BQ; q++) {
                float4 t4 = bR[q];
                t4.x = to_tf32(t4.x); t4.y = to_tf32(t4.y);
                t4.z = to_tf32(t4.z); t4.w = to_tf32(t4.w);
                *(float4*)(Bsb2 + (bkr + q * BKR) * BSTR + bnc) = t4;
            }
            __syncthreads();
            cur = nxt;
        }
    }

    // epilogue: c0/c1 at (row, 2lc), c2/c3 at (row+8, 2lc)
#pragma unroll
    for (int mt = 0; mt < MT; mt++) {
        const int r0 = bm * BM + wM * WM + mt * 16 + lr;
#pragma unroll
        for (int nt = 0; nt < NT; nt++) {
            const int col = bn * BN + wN * WN + nt * 8 + lc * 2;
            float2 o0, o1;
            o0.x = epi_apply<EPI>(acc[mt][nt][0]);
            o0.y = epi_apply<EPI>(acc[mt][nt][1]);
            o1.x = epi_apply<EPI>(acc[mt][nt][2]);
            o1.y = epi_apply<EPI>(acc[mt][nt][3]);
            *(float2*)(C + (size_t)r0 * N + col) = o0;
            *(float2*)(C + (size_t)(r0 + 8) * N + col) = o1;
        }
    }
}

// ---------------------------------------------------------------------------
// decay w and in-context lr a:  one thread per (token, head)
// ---------------------------------------------------------------------------
__global__ void wa_kernel(const float* __restrict__ hw, const float* __restrict__ ha,
                          const float* __restrict__ w2, const float* __restrict__ a2,
                          const float* __restrict__ w0, const float* __restrict__ a0,
                          float* __restrict__ wout, float* __restrict__ aout) {
    const int idx = blockIdx.x * blockDim.x + threadIdx.x;
    const int token = idx >> 4;
    const int h = idx & 15;
    const float* hwr = hw + (size_t)token * 64;
    const float* har = ha + (size_t)token * 64;
    float sw = 0.f, sa = 0.f;
#pragma unroll
    for (int kx = 0; kx < 64; kx++) {
        sw = fmaf(hwr[kx], w2[kx * HH + h], sw);
        sa = fmaf(har[kx], a2[kx * HH + h], sa);
    }
    const float zw = w0[h] + sw;
    wout[idx] = 0.60653065971263342f / (1.f + expf(-zw));   // e^{-0.5} * sigmoid
    aout[idx] = 1.f / (1.f + expf(-(a0[h] + sa)));
}

// ---------------------------------------------------------------------------
// kk = normalize((k*k_k) per head), kv = kk * v * a.  One warp per (token,h).
// kkout may alias k (read-before-write at identical indices).
// ---------------------------------------------------------------------------
__global__ void kv_kernel(const float* __restrict__ k, const float* __restrict__ v,
                          const float* __restrict__ k_k, const float* __restrict__ abuf,
                          float* __restrict__ kkout, float* __restrict__ kvout) {
    const int gw = (blockIdx.x * blockDim.x + threadIdx.x) >> 5;
    const int lane = threadIdx.x & 31;
    const int token = gw >> 4;
    const int h = gw & 15;
    const size_t base = (size_t)token * CC + h * DD;
    const int c0 = h * DD + lane, c1 = c0 + 32;

    float k0 = k[base + lane]       * k_k[c0];
    float k1 = k[base + lane + 32]  * k_k[c1];
    float ss = k0 * k0 + k1 * k1;
#pragma unroll
    for (int o = 16; o; o >>= 1) ss += __shfl_xor_sync(0xffffffffu, ss, o);
    const float inv = 1.f / fmaxf(sqrtf(ss), 1e-12f);
    k0 *= inv; k1 *= inv;
    const float a = abuf[(size_t)token * HH + h];
    const float vv0 = v[base + lane], vv1 = v[base + lane + 32];
    kkout[base + lane]      = k0;
    kkout[base + lane + 32] = k1;
    kvout[base + lane]      = k0 * vv0 * a;
    kvout[base + lane + 32] = k1 * vv1 * a;
}

// ---------------------------------------------------------------------------
// WKV scan: state = state * w_t + kv_t. One block per (b,h), 64 threads.
// wkv may alias kv (each element read once, then overwritten).
// ---------------------------------------------------------------------------
__global__ void scan_kernel(const float* __restrict__ kv, const float* __restrict__ wdec,
                            float* __restrict__ wkv) {
    const int bh = blockIdx.x;            // 0..127
    const int b = bh >> 4, h = bh & 15;
    const int d = threadIdx.x;            // 0..63
    const size_t base = (size_t)b * TT * CC + (size_t)h * DD + d;
    const float* kvp = kv + base;
    float* op = wkv + base;
    const float* wp = wdec + (size_t)b * TT * HH + h;
    float state = 0.f;
#pragma unroll 16
    for (int t = 0; t < TT; t++) {
        const float w = wp[(size_t)t * HH];
        const float x = kvp[(size_t)t * CC];
        state = fmaf(state, w, x);
        op[(size_t)t * CC] = state;
    }
}

// ---------------------------------------------------------------------------
// Fused epilogue: bonus + GroupNorm + affine + gate. One warp per (token,h).
// xng may alias g (read-before-write at identical indices).
// ---------------------------------------------------------------------------
__global__ void epi_kernel(const float* __restrict__ wkv, const float* __restrict__ r,
                           const float* __restrict__ kk, const float* __restrict__ v,
                           const float* __restrict__ r_k, const float* __restrict__ g,
                           const float* __restrict__ lnw, const float* __restrict__ lnb,
                           float* __restrict__ xng) {
    const int gw = (blockIdx.x * blockDim.x + threadIdx.x) >> 5;
    const int lane = threadIdx.x & 31;
    const int token = gw >> 4;
    const int h = gw & 15;
    const size_t base = (size_t)token * CC + h * DD;
    const int c0 = h * DD + lane, c1 = c0 + 32;

    const float s0 = wkv[base + lane],      s1 = wkv[base + lane + 32];
    const float r0 = r[base + lane],        r1 = r[base + lane + 32];
    const float q0 = kk[base + lane],       q1 = kk[base + lane + 32];
    const float v0 = v[base + lane],        v1 = v[base + lane + 32];
    const float g0 = g[base + lane],        g1v = g[base + lane + 32];

    float bsum = r0 * q0 * r_k[c0] + r1 * q1 * r_k[c1];
#pragma unroll
    for (int o = 16; o; o >>= 1) bsum += __shfl_xor_sync(0xffffffffu, bsum, o);

    const float x0 = fmaf(bsum, v0, s0 * r0);
    const float x1 = fmaf(bsum, v1, s1 * r1);

    float ms = x0 + x1;
    float vs = x0 * x0 + x1 * x1;
#pragma unroll
    for (int o = 16; o; o >>= 1) {
        ms += __shfl_xor_sync(0xffffffffu, ms, o);
        vs += __shfl_xor_sync(0xffffffffu, vs, o);
    }
    const float mean = ms * (1.f / 64.f);
    const float var  = vs * (1.f / 64.f) - mean * mean;
    const float rs = rsqrtf(var + 1e-5f);

    xng[base + lane]      = fmaf((x0 - mean) * rs, lnw[c0], lnb[c0]) * g0;
    xng[base + lane + 32] = fmaf((x1 - mean) * rs, lnw[c1], lnb[c1]) * g1v;
}

// ---------------------------------------------------------------------------
// Host launch
// ---------------------------------------------------------------------------
extern "C" void kernel_launch(void* const* d_in, const int* in_sizes, int n_in,
                              void* d_out, int out_size) {
    (void)in_sizes; (void)n_in; (void)out_size;
    const float* x   = (const float*)d_in[0];
    const float* x_r = (const float*)d_in[1];
    const float* x_w = (const float*)d_in[2];
    const float* x_k = (const float*)d_in[3];
    const float* x_v = (const float*)d_in[4];
    const float* x_a = (const float*)d_in[5];
    const float* x_g = (const float*)d_in[6];
    const float* w0  = (const float*)d_in[7];
    const float* w2  = (const float*)d_in[9];
    const float* w1  = (const float*)d_in[8];
    const float* a0  = (const float*)d_in[10];
    const float* a1  = (const float*)d_in[11];
    const float* a2  = (const float*)d_in[12];
    // d_in[13..15] = v0, v1, v2 : mathematically a no-op in the reference
    const float* g1  = (const float*)d_in[16];
    const float* g2  = (const float*)d_in[17];
    const float* k_k = (const float*)d_in[18];
    const float* r_k = (const float*)d_in[19];
    const float* Wr  = (const float*)d_in[20];
    const float* Wk  = (const float*)d_in[21];
    const float* Wv  = (const float*)d_in[22];
    const float* Wo  = (const float*)d_in[23];
    const float* lnw = (const float*)d_in[24];
    const float* lnb = (const float*)d_in[25];
    float* out = (float*)d_out;

    float* scr = nullptr;
    cudaGetSymbolAddress((void**)&scr, g_scr);

    float* rB   = scr + OFF_R;
    float* kB   = scr + OFF_K;      // becomes kk in-place
    float* vB   = scr + OFF_V;
    float* gate = scr + OFF_GATE;   // becomes xng in-place
    float* kvB  = scr + OFF_KV;     // becomes wkv in-place
    float* hw   = scr + OFF_HW;
    float* ha   = scr + OFF_HA;
    float* hg   = scr + OFF_HG;
    float* wd   = scr + OFF_WD;
    float* ab   = scr + OFF_AB;

    // dynamic smem sizes (bytes)
    constexpr int SM128 = (2 * 128 * 36 + 2 * 32 * 136) * 4;   // 71680
    constexpr int SM64  = (2 * 128 * 36 + 2 * 32 * 72) * 4;    // 55296

    cudaFuncSetAttribute(mma_gemm<128, EPI_NONE, true>,
                         cudaFuncAttributeMaxDynamicSharedMemorySize, SM128);
    cudaFuncSetAttribute(mma_gemm<128, EPI_NONE, false>,
                         cudaFuncAttributeMaxDynamicSharedMemorySize, SM128);
    cudaFuncSetAttribute(mma_gemm<128, EPI_SIG, false>,
                         cudaFuncAttributeMaxDynamicSharedMemorySize, SM128);
    cudaFuncSetAttribute(mma_gemm<64, EPI_TANH, true>,
                         cudaFuncAttributeMaxDynamicSharedMemorySize, SM64);

    const dim3 gridBig(CC / 128, BT / 128);       // (8, 128)
    const dim3 gridLora(1, BT / 128);             // (1, 128)

    // 1) big projections with fused token-shift mix (tf32 MMA)
    mma_gemm<128, EPI_NONE, true><<<gridBig, 256, SM128>>>(x, x_r, Wr, rB, BT, CC, CC);
    mma_gemm<128, EPI_NONE, true><<<gridBig, 256, SM128>>>(x, x_k, Wk, kB, BT, CC, CC);
    mma_gemm<128, EPI_NONE, true><<<gridBig, 256, SM128>>>(x, x_v, Wv, vB, BT, CC, CC);

    // 2) lora stage 1 (tanh fused)
    mma_gemm<64, EPI_TANH, true><<<gridLora, 256, SM64>>>(x, x_w, w1, hw, BT, DLOW, CC);
    mma_gemm<64, EPI_TANH, true><<<gridLora, 256, SM64>>>(x, x_a, a1, ha, BT, DLOW, CC);
    mma_gemm<64, EPI_TANH, true><<<gridLora, 256, SM64>>>(x, x_g, g1, hg, BT, DLOW, CC);

    // 3) decay + in-context lr
    wa_kernel<<<(BT * HH) / 256, 256>>>(hw, ha, w2, a2, w0, a0, wd, ab);

    // 4) gate stage 2 (sigmoid fused)
    mma_gemm<128, EPI_SIG, false><<<gridBig, 256, SM128>>>(hg, nullptr, g2, gate, BT, CC, DLOW);

    // 5) kk normalize + kv  (kk overwrites k in-place)
    kv_kernel<<<(BT * HH) / 8, 256>>>(kB, vB, k_k, ab, kB, kvB);

    // 6) WKV recurrence (wkv overwrites kv in-place)
    scan_kernel<<<8 * HH, 64>>>(kvB, wd, kvB);

    // 7) bonus + GroupNorm + gate (xng overwrites gate in-place)
    epi_kernel<<<(BT * HH) / 8, 256>>>(kvB, rB, kB, vB, r_k, gate, lnw, lnb, gate);

    // 8) output projection
    mma_gemm<128, EPI_NONE, false><<<gridBig, 256, SM128>>>(gate, nullptr, Wo, out, BT, CC, CC);
}